// round 5
// baseline (speedup 1.0000x reference)
#include <cuda_runtime.h>
#include <cuda_bf16.h>

#define B_ 128
#define T_ 512
#define E_ 256
#define U_ 256

typedef unsigned long long u64t;

// 64MB scratch: xw[t][b][u]
__device__ __align__(16) float g_xw[T_ * B_ * U_];

__device__ __forceinline__ u64t ffma2(u64t a, u64t b, u64t c) {
    u64t d;
    asm("fma.rn.f32x2 %0, %1, %2, %3;" : "=l"(d) : "l"(a), "l"(b), "l"(c));
    return d;
}
__device__ __forceinline__ float f2lo(u64t v) { return __uint_as_float((unsigned)(v & 0xffffffffull)); }
__device__ __forceinline__ float f2hi(u64t v) { return __uint_as_float((unsigned)(v >> 32)); }
__device__ __forceinline__ u64t pk2(float lo, float hi) {
    u64t r;
    asm("mov.b64 %0, {%1, %2};" : "=l"(r) : "f"(lo), "f"(hi));
    return r;
}
__device__ __forceinline__ float tanh_fast(float x) {
    float ex = __expf(2.0f * x);
    return 1.0f - __fdividef(2.0f, ex + 1.0f);
}

// ---------------- mbarrier / cluster helpers ----------------
__device__ __forceinline__ void mbar_init(unsigned addr, unsigned cnt) {
    asm volatile("mbarrier.init.shared.b64 [%0], %1;" :: "r"(addr), "r"(cnt) : "memory");
}
__device__ __forceinline__ void mbar_expect(unsigned addr, unsigned bytes) {
    asm volatile("mbarrier.arrive.expect_tx.shared.b64 _, [%0], %1;"
                 :: "r"(addr), "r"(bytes) : "memory");
}
__device__ __forceinline__ void mbar_wait(unsigned addr, unsigned parity) {
    unsigned done;
    asm volatile(
        "{\n\t.reg .pred p;\n\t"
        "mbarrier.try_wait.parity.acquire.cta.shared::cta.b64 p, [%1], %2;\n\t"
        "selp.b32 %0, 1, 0, p;\n\t}"
        : "=r"(done) : "r"(addr), "r"(parity) : "memory");
    if (!done) {
        asm volatile(
            "{\n\t.reg .pred P1;\n\t"
            "W_%=:\n\t"
            "mbarrier.try_wait.parity.acquire.cta.shared::cta.b64 P1, [%0], %1, 0x989680;\n\t"
            "@P1 bra D_%=;\n\t"
            "bra W_%=;\n\t"
            "D_%=:\n\t}"
            :: "r"(addr), "r"(parity) : "memory");
    }
}
__device__ __forceinline__ void st_async_b64(unsigned raddr, u64t v, unsigned rbar) {
    asm volatile("st.async.shared::cluster.mbarrier::complete_tx::bytes.b64 [%0], %1, [%2];"
                 :: "r"(raddr), "l"(v), "r"(rbar) : "memory");
}
__device__ __forceinline__ void st_cluster_f32(unsigned raddr, float v) {
    asm volatile("st.shared::cluster.f32 [%0], %1;" :: "r"(raddr), "f"(v) : "memory");
}
__device__ __forceinline__ void cluster_sync_() {
    asm volatile("barrier.cluster.arrive.aligned;" ::: "memory");
    asm volatile("barrier.cluster.wait.aligned;" ::: "memory");
}

// ---------------------------------------------------------------------------
// Phase 1: xw[t][b][u] = sum_e emb[sentence[b][t]][e] * W[u][e]  (unchanged)
// ---------------------------------------------------------------------------
__global__ void __launch_bounds__(256)
xw_kernel(const int* __restrict__ sent, const float* __restrict__ emb,
          const float* __restrict__ Wm)
{
    __shared__ __align__(16) float2 As2[16 * 64];
    __shared__ __align__(16) float  Bs[16 * 256];
    __shared__ int idx[64];

    const int tid = threadIdx.x;
    const int r0 = blockIdx.x * 64;
    const int t  = r0 >> 7;
    const int b0 = r0 & 127;

    if (tid < 64) idx[tid] = sent[(b0 + tid) * T_ + t];
    __syncthreads();

    const int tx = tid & 15;
    const int ty = tid >> 4;
    const int arow = tid >> 2;
    const int aq = tid & 3;

    u64t acc[4][8];
    #pragma unroll
    for (int i = 0; i < 4; i++)
        #pragma unroll
        for (int p = 0; p < 8; p++) acc[i][p] = 0ull;

    float4 va = *(const float4*)(emb + (size_t)idx[arow] * E_ + aq * 4);
    float4 vb0 = *(const float4*)(Wm + (size_t)tid * E_ + 0);
    float4 vb1 = *(const float4*)(Wm + (size_t)tid * E_ + 4);
    float4 vb2 = *(const float4*)(Wm + (size_t)tid * E_ + 8);
    float4 vb3 = *(const float4*)(Wm + (size_t)tid * E_ + 12);

    for (int ko = 0; ko < 16; ko++) {
        if (ko > 0) __syncthreads();

        As2[(aq * 4 + 0) * 64 + arow] = make_float2(va.x, va.x);
        As2[(aq * 4 + 1) * 64 + arow] = make_float2(va.y, va.y);
        As2[(aq * 4 + 2) * 64 + arow] = make_float2(va.z, va.z);
        As2[(aq * 4 + 3) * 64 + arow] = make_float2(va.w, va.w);
        {
            const float v[16] = {vb0.x, vb0.y, vb0.z, vb0.w, vb1.x, vb1.y, vb1.z, vb1.w,
                                 vb2.x, vb2.y, vb2.z, vb2.w, vb3.x, vb3.y, vb3.z, vb3.w};
            #pragma unroll
            for (int j = 0; j < 16; j++) Bs[j * 256 + tid] = v[j];
        }
        __syncthreads();

        if (ko < 15) {
            const int kb = (ko + 1) * 16;
            va  = *(const float4*)(emb + (size_t)idx[arow] * E_ + kb + aq * 4);
            vb0 = *(const float4*)(Wm + (size_t)tid * E_ + kb + 0);
            vb1 = *(const float4*)(Wm + (size_t)tid * E_ + kb + 4);
            vb2 = *(const float4*)(Wm + (size_t)tid * E_ + kb + 8);
            vb3 = *(const float4*)(Wm + (size_t)tid * E_ + kb + 12);
        }

        #pragma unroll
        for (int k = 0; k < 16; k++) {
            u64t ap[4];
            #pragma unroll
            for (int i = 0; i < 4; i++)
                ap[i] = *(const u64t*)&As2[k * 64 + ty * 4 + i];
            #pragma unroll
            for (int q = 0; q < 4; q++) {
                const ulonglong2 bq = *(const ulonglong2*)&Bs[k * 256 + q * 64 + tx * 4];
                #pragma unroll
                for (int i = 0; i < 4; i++) {
                    acc[i][2 * q + 0] = ffma2(bq.x, ap[i], acc[i][2 * q + 0]);
                    acc[i][2 * q + 1] = ffma2(bq.y, ap[i], acc[i][2 * q + 1]);
                }
            }
        }
    }

    #pragma unroll
    for (int i = 0; i < 4; i++) {
        const int rg = r0 + ty * 4 + i;
        #pragma unroll
        for (int q = 0; q < 4; q++) {
            float4 o;
            o.x = f2lo(acc[i][2 * q + 0]); o.y = f2hi(acc[i][2 * q + 0]);
            o.z = f2lo(acc[i][2 * q + 1]); o.w = f2hi(acc[i][2 * q + 1]);
            __stcs((float4*)(g_xw + (size_t)rg * U_ + q * 64 + tx * 4), o);
        }
    }
}

// ---------------------------------------------------------------------------
// Phase 2: recurrence, partial-exchange scheme.
// Cluster of 2 CTAs per batch pair. CTA r keeps U[:, j in its half] so each
// step's dot needs ONLY the locally-computed h-half; only 1KB of partials
// crosses the cluster (st.async + tx mbarrier). Thread t owns u-row t for
// both batch rows; h reads are warp-broadcast (conflict-free); no shfl.
// ---------------------------------------------------------------------------
__global__ void __cluster_dims__(2, 1, 1) __launch_bounds__(256, 1)
rnn_kernel(const float* __restrict__ Um,
           const float* __restrict__ W1, const float* __restrict__ b1v,
           const float* __restrict__ W2, const float* __restrict__ b2v,
           float* __restrict__ outp)
{
    __shared__ __align__(16) float hbuf[2][2][128];     // [buf][row][j-local]
    __shared__ __align__(16) u64t  pbuf[2][128];        // [buf][i] packed (p0,p1)
    __shared__ __align__(8)  unsigned long long mbar[2];
    __shared__ __align__(16) float hfin[2][256];        // final h, rank0 only used
    __shared__ float hid[2][32];

    const int tid = threadIdx.x;
    unsigned rank;
    asm("mov.u32 %0, %%cluster_ctarank;" : "=r"(rank));
    const unsigned peer = rank ^ 1u;
    const int b0 = (blockIdx.x >> 1) * 2;
    const int jbase = (int)rank * 128;          // my j-half == my h-half
    const int i = tid & 127;
    const bool owner = ((tid >> 7) == (int)rank);
    const bool lead = (tid == (int)rank * 128);

    // U[u = tid, j = jbase .. jbase+127] into 64 u64 regs
    u64t Ur[64];
    {
        const u64t* p = (const u64t*)(Um + (size_t)tid * U_ + jbase);
        #pragma unroll
        for (int q = 0; q < 64; q++) Ur[q] = p[q];
    }

    for (int k = tid; k < 512; k += 256) ((float*)hbuf)[k] = 0.0f;

    const unsigned lh = (unsigned)__cvta_generic_to_shared(pbuf);
    const unsigned lb = (unsigned)__cvta_generic_to_shared(mbar);
    const unsigned lf = (unsigned)__cvta_generic_to_shared(hfin);
    unsigned rp, rb_, r0f;
    asm("mapa.shared::cluster.u32 %0, %1, %2;" : "=r"(rp)  : "r"(lh), "r"(peer));
    asm("mapa.shared::cluster.u32 %0, %1, %2;" : "=r"(rb_) : "r"(lb), "r"(peer));
    asm("mapa.shared::cluster.u32 %0, %1, %2;" : "=r"(r0f) : "r"(lf), "r"(0u));  // rank0's hfin

    if (lead) {
        mbar_init(lb + 0, 1);
        mbar_init(lb + 8, 1);
        mbar_expect(lb + 0, 1024);   // arm for step 0
        mbar_expect(lb + 8, 1024);   // arm for step 1
    }
    __syncthreads();
    cluster_sync_();                 // peer init visible before any st.async

    unsigned ph[2] = {0u, 0u};
    float cxw0 = 0.0f, cxw1 = 0.0f;
    if (owner) {
        cxw0 = __ldcs(g_xw + (size_t)b0 * U_ + tid);
        cxw1 = __ldcs(g_xw + (size_t)(b0 + 1) * U_ + tid);
    }
    float v0 = 0.0f, v1 = 0.0f;

    for (int t = 0; t < T_; t++) {
        const int rb = t & 1;
        const int wb = rb ^ 1;

        // dot over my j-half for both rows; h reads broadcast across the warp
        u64t a0[4] = {0ull, 0ull, 0ull, 0ull};
        u64t a1[4] = {0ull, 0ull, 0ull, 0ull};
        {
            const ulonglong2* h0p = (const ulonglong2*)&hbuf[rb][0][0];
            const ulonglong2* h1p = (const ulonglong2*)&hbuf[rb][1][0];
            #pragma unroll
            for (int q = 0; q < 32; q++) {
                const ulonglong2 h0 = h0p[q];
                const ulonglong2 h1 = h1p[q];
                a0[(2*q)   & 3] = ffma2(Ur[2*q],     h0.x, a0[(2*q)   & 3]);
                a0[(2*q+1) & 3] = ffma2(Ur[2*q + 1], h0.y, a0[(2*q+1) & 3]);
                a1[(2*q)   & 3] = ffma2(Ur[2*q],     h1.x, a1[(2*q)   & 3]);
                a1[(2*q+1) & 3] = ffma2(Ur[2*q + 1], h1.y, a1[(2*q+1) & 3]);
            }
        }
        const u64t s0 = ffma2(a0[0], pk2(1.f,1.f), a0[1]);  // cheap pairwise
        const u64t s1 = ffma2(a0[2], pk2(1.f,1.f), a0[3]);
        const u64t s2 = ffma2(a1[0], pk2(1.f,1.f), a1[1]);
        const u64t s3 = ffma2(a1[2], pk2(1.f,1.f), a1[3]);
        const float p0 = (f2lo(s0) + f2hi(s0)) + (f2lo(s1) + f2hi(s1));
        const float p1 = (f2lo(s2) + f2hi(s2)) + (f2lo(s3) + f2hi(s3));

        if (!owner) {
            // my u is in the peer's owner half: ship packed partials
            st_async_b64(rp + (unsigned)(rb * 128 + i) * 8, pk2(p0, p1), rb_ + rb * 8);
        } else {
            // prefetch next step's xw while waiting
            const int tn = (t + 1 < T_) ? t + 1 : t;
            const float nxw0 = __ldcs(g_xw + (size_t)tn * (B_ * U_) + b0 * U_ + tid);
            const float nxw1 = __ldcs(g_xw + (size_t)tn * (B_ * U_) + (b0 + 1) * U_ + tid);

            mbar_wait(lb + rb * 8, ph[rb]);
            ph[rb] ^= 1u;
            if (lead) mbar_expect(lb + rb * 8, 1024);   // re-arm for step t+2

            const u64t pp = pbuf[rb][i];
            v0 = tanh_fast(p0 + f2lo(pp) + cxw0);
            v1 = tanh_fast(p1 + f2hi(pp) + cxw1);
            hbuf[wb][0][i] = v0;
            hbuf[wb][1][i] = v1;
            cxw0 = nxw0; cxw1 = nxw1;
        }
        __syncthreads();
    }

    // ship final h (in owner regs v0,v1) to rank0's hfin, then head on rank0
    if (owner) {
        st_cluster_f32(r0f + (unsigned)(jbase + i) * 4,       v0);
        st_cluster_f32(r0f + (unsigned)(256 + jbase + i) * 4, v1);
    }
    cluster_sync_();

    if (rank == 0) {
        if (tid < 32) {
            for (int bi = 0; bi < 2; bi++) {
                float acc = b1v[tid];
                const float* hr = hfin[bi];
                #pragma unroll 8
                for (int j = 0; j < 256; j++)
                    acc = fmaf(hr[j], __ldg(W1 + j * 32 + tid), acc);
                hid[bi][tid] = fmaxf(acc, 0.0f);
            }
        }
        __syncthreads();
        if (tid < 2) {
            float l0 = b2v[0], l1 = b2v[1];
            #pragma unroll
            for (int k = 0; k < 32; k++) {
                const float hv = hid[tid][k];
                l0 = fmaf(hv, __ldg(W2 + k * 2 + 0), l0);
                l1 = fmaf(hv, __ldg(W2 + k * 2 + 1), l1);
            }
            const float m = fmaxf(l0, l1);
            const float e0 = expf(l0 - m);
            const float e1 = expf(l1 - m);
            const float inv = 1.0f / (e0 + e1);
            outp[(b0 + tid) * 2 + 0] = e0 * inv;
            outp[(b0 + tid) * 2 + 1] = e1 * inv;
        }
    }
    cluster_sync_();   // no CTA exits while peer traffic may be in flight
}

// ---------------------------------------------------------------------------
extern "C" void kernel_launch(void* const* d_in, const int* in_sizes, int n_in,
                              void* d_out, int out_size)
{
    const int*   sent = (const int*)d_in[0];
    const float* emb  = (const float*)d_in[1];
    const float* Wm   = (const float*)d_in[2];
    const float* Um   = (const float*)d_in[3];
    const float* W1   = (const float*)d_in[4];
    const float* b1v  = (const float*)d_in[5];
    const float* W2   = (const float*)d_in[6];
    const float* b2v  = (const float*)d_in[7];
    float* outp = (float*)d_out;
    (void)in_sizes; (void)n_in; (void)out_size;

    xw_kernel<<<1024, 256>>>(sent, emb, Wm);
    rnn_kernel<<<128, 256>>>(Um, W1, b1v, W2, b2v, outp);
}